// round 1
// baseline (speedup 1.0000x reference)
#include <cuda_runtime.h>
#include <math.h>

// ---------------------------------------------------------------------------
// EdgeGatedMPNNLayer — GB300 (sm_103a)
//
// Restructure: edge-gate GEMM [E,258]@[258,128] is decomposed into two node
// GEMMs (A = x@Wg1[0:128], B = x@Wg1[128:256], both with BN scale folded in)
// plus per-edge elementwise work. Messages scatter via atomicAdd (RED).
// ---------------------------------------------------------------------------

#define DIM 128
#define MAXN 50000
#define EPS 1e-5f

#define BM 64
#define XS_STRIDE 132
#define SMEM_BYTES (DIM*DIM*4 + BM*XS_STRIDE*4)   // 65536 + 33792 = 99328 B

// scratch (device globals — no allocation allowed)
__device__ float g_xj [MAXN*DIM];
__device__ float g_A  [MAXN*DIM];
__device__ float g_B  [MAXN*DIM];
__device__ float g_agg[MAXN*DIM];
__device__ float g_params[3*DIM];   // we0[128], we1[128], cbias[128]

__device__ __forceinline__ float gelu_exact(float v) {
    return 0.5f * v * (1.0f + erff(v * 0.70710678118654752f));
}

// ---------------------------------------------------------------------------
// Fold BN scale into edge-feat weight rows + combined bias:
//   s = gamma * rsqrt(var+eps);  t = beta - mean*s
//   we0 = Wg1[256,:]*s; we1 = Wg1[257,:]*s; cbias = b_g1*s + t
// ---------------------------------------------------------------------------
__global__ void param_kernel(const float* __restrict__ Wg1, const float* __restrict__ bg1,
                             const float* __restrict__ bng, const float* __restrict__ bnb,
                             const float* __restrict__ bnm, const float* __restrict__ bnv)
{
    int n = threadIdx.x;
    if (n < DIM) {
        float s = bng[n] * rsqrtf(bnv[n] + EPS);
        g_params[n]         = Wg1[256*DIM + n] * s;
        g_params[DIM + n]   = Wg1[257*DIM + n] * s;
        g_params[2*DIM + n] = bg1[n]*s + (bnb[n] - bnm[n]*s);
    }
}

// ---------------------------------------------------------------------------
// Node GEMM: C[M,128] = X[M,128] @ W[128,128], per-column scale+bias epilogue.
// grid.y = mode: 0 -> xj (bias b_phi), 1 -> A (scale s), 2 -> B (scale s)
// Block 256 threads, tile 64 rows x 128 cols, thread = 4 rows x 8 cols.
// ---------------------------------------------------------------------------
__global__ void __launch_bounds__(256) node_gemm(
    const float* __restrict__ x,
    const float* __restrict__ Wphi, const float* __restrict__ bphi,
    const float* __restrict__ Wg1,
    const float* __restrict__ bng,  const float* __restrict__ bnv,
    int M)
{
    extern __shared__ float sm[];
    float* Ws = sm;               // [128][128]
    float* Xs = sm + DIM*DIM;     // [64][132]

    int mode = blockIdx.y;
    const float* W = (mode == 0) ? Wphi : (mode == 1 ? Wg1 : Wg1 + DIM*DIM);
    float* C       = (mode == 0) ? g_xj : (mode == 1 ? g_A : g_B);

    int m0 = blockIdx.x * BM;
    int t  = threadIdx.x;

    // load W (16384 floats) via float4, flat
    {
        const float4* Wv  = (const float4*)W;
        float4*       Wsv = (float4*)Ws;
        #pragma unroll
        for (int i = 0; i < 16; i++) Wsv[t + i*256] = Wv[t + i*256];
    }
    // load X tile (64 rows x 32 float4), rows padded to stride 132
    #pragma unroll
    for (int i = 0; i < 8; i++) {
        int idx = t + i*256;
        int row = idx >> 5;
        int c4  = idx & 31;
        float4 v = make_float4(0.f, 0.f, 0.f, 0.f);
        int grow = m0 + row;
        if (grow < M) v = ((const float4*)x)[(size_t)grow*32 + c4];
        *(float4*)(Xs + row*XS_STRIDE + c4*4) = v;
    }
    __syncthreads();

    int rg = t >> 4, cg = t & 15;
    float acc[4][8];
    #pragma unroll
    for (int i = 0; i < 4; i++)
        #pragma unroll
        for (int j = 0; j < 8; j++) acc[i][j] = 0.f;

    #pragma unroll 8
    for (int k = 0; k < DIM; k++) {
        float xv[4];
        #pragma unroll
        for (int i = 0; i < 4; i++) xv[i] = Xs[(rg*4 + i)*XS_STRIDE + k];
        #pragma unroll
        for (int j = 0; j < 8; j++) {
            float wv = Ws[k*DIM + cg + 16*j];
            #pragma unroll
            for (int i = 0; i < 4; i++) acc[i][j] = fmaf(xv[i], wv, acc[i][j]);
        }
    }

    #pragma unroll
    for (int j = 0; j < 8; j++) {
        int col = cg + 16*j;
        float sc, bs;
        if (mode == 0) { sc = 1.f; bs = bphi[col]; }
        else           { sc = bng[col] * rsqrtf(bnv[col] + EPS); bs = 0.f; }
        #pragma unroll
        for (int i = 0; i < 4; i++) {
            int row = m0 + rg*4 + i;
            if (row < M) C[(size_t)row*DIM + col] = fmaf(acc[i][j], sc, bs);
        }
    }
}

// ---------------------------------------------------------------------------
// Edge kernel: warp-per-edge, lane owns 4 features (float4).
//   h = A[dst] + B[src] + ef0*we0 + ef1*we1 + cbias
//   gate = sigmoid(dot(gelu(h), Wg2) + b_g2)
//   atomicAdd(agg[dst], xj[src] * (w * gate))
// ---------------------------------------------------------------------------
__global__ void __launch_bounds__(256) edge_kernel(
    const int* __restrict__ ei, const float* __restrict__ ew,
    const float* __restrict__ ef, const float* __restrict__ Wg2,
    const float* __restrict__ bg2, int E)
{
    int lane = threadIdx.x & 31;
    int warp = (blockIdx.x * blockDim.x + threadIdx.x) >> 5;
    int nw   = (gridDim.x * blockDim.x) >> 5;

    float4 we0 = ((const float4*)(g_params          ))[lane];
    float4 we1 = ((const float4*)(g_params +     DIM))[lane];
    float4 cb  = ((const float4*)(g_params + 2 * DIM))[lane];
    float4 w2  = ((const float4*)Wg2)[lane];
    float  b2  = bg2[0];

    for (int e = warp; e < E; e += nw) {
        int   src = ei[e];
        int   dst = ei[E + e];
        float w   = ew[e];
        float2 efv = ((const float2*)ef)[e];

        float4 a = ((const float4*)g_A)[(size_t)dst*32 + lane];
        float4 b = ((const float4*)g_B)[(size_t)src*32 + lane];

        float4 h;
        h.x = a.x + b.x + efv.x*we0.x + efv.y*we1.x + cb.x;
        h.y = a.y + b.y + efv.x*we0.y + efv.y*we1.y + cb.y;
        h.z = a.z + b.z + efv.x*we0.z + efv.y*we1.z + cb.z;
        h.w = a.w + b.w + efv.x*we0.w + efv.y*we1.w + cb.w;

        h.x = gelu_exact(h.x);
        h.y = gelu_exact(h.y);
        h.z = gelu_exact(h.z);
        h.w = gelu_exact(h.w);

        float d = h.x*w2.x + h.y*w2.y + h.z*w2.z + h.w*w2.w;
        #pragma unroll
        for (int off = 16; off > 0; off >>= 1)
            d += __shfl_xor_sync(0xffffffffu, d, off);

        float gate = 1.f / (1.f + __expf(-(d + b2)));
        float c = w * gate;

        float4 xs = ((const float4*)g_xj)[(size_t)src*32 + lane];
        float* p = g_agg + (size_t)dst*DIM + lane*4;
        atomicAdd(p + 0, xs.x * c);
        atomicAdd(p + 1, xs.y * c);
        atomicAdd(p + 2, xs.z * c);
        atomicAdd(p + 3, xs.w * c);
    }
}

// ---------------------------------------------------------------------------
// Update GEMM + fused epilogue:
//   acc = agg @ Wu[128:256] + x @ Wu[0:128]     (x done LAST so Xs holds x)
//   h = gelu(acc + b_u); y = x + h; out = LayerNorm(y) * lng + lnb
// ---------------------------------------------------------------------------
__global__ void __launch_bounds__(256) update_kernel(
    const float* __restrict__ x, const float* __restrict__ Wu,
    const float* __restrict__ bu,
    const float* __restrict__ lng, const float* __restrict__ lnb,
    float* __restrict__ out, int M)
{
    extern __shared__ float sm[];
    float* Ws = sm;
    float* Xs = sm + DIM*DIM;

    int m0 = blockIdx.x * BM;
    int t  = threadIdx.x;
    int rg = t >> 4, cg = t & 15;

    float acc[4][8];
    #pragma unroll
    for (int i = 0; i < 4; i++)
        #pragma unroll
        for (int j = 0; j < 8; j++) acc[i][j] = 0.f;

    #pragma unroll
    for (int p = 0; p < 2; p++) {
        const float* src = (p == 0) ? (const float*)g_agg : x;
        const float* W   = Wu + ((p == 0) ? DIM*DIM : 0);
        if (p) __syncthreads();   // previous phase compute done before overwrite

        {
            const float4* Wv  = (const float4*)W;
            float4*       Wsv = (float4*)Ws;
            #pragma unroll
            for (int i = 0; i < 16; i++) Wsv[t + i*256] = Wv[t + i*256];
        }
        #pragma unroll
        for (int i = 0; i < 8; i++) {
            int idx = t + i*256;
            int row = idx >> 5;
            int c4  = idx & 31;
            float4 v = make_float4(0.f, 0.f, 0.f, 0.f);
            int grow = m0 + row;
            if (grow < M) v = ((const float4*)src)[(size_t)grow*32 + c4];
            *(float4*)(Xs + row*XS_STRIDE + c4*4) = v;
        }
        __syncthreads();

        #pragma unroll 8
        for (int k = 0; k < DIM; k++) {
            float xv[4];
            #pragma unroll
            for (int i = 0; i < 4; i++) xv[i] = Xs[(rg*4 + i)*XS_STRIDE + k];
            #pragma unroll
            for (int j = 0; j < 8; j++) {
                float wv = Ws[k*DIM + cg + 16*j];
                #pragma unroll
                for (int i = 0; i < 4; i++) acc[i][j] = fmaf(xv[i], wv, acc[i][j]);
            }
        }
    }

    // epilogue: Xs holds the x tile (phase 1 was x). Build y, reduce, normalize.
    float sums[4] = {0.f, 0.f, 0.f, 0.f};
    float sqs [4] = {0.f, 0.f, 0.f, 0.f};
    #pragma unroll
    for (int j = 0; j < 8; j++) {
        int col = cg + 16*j;
        float bb = bu[col];
        #pragma unroll
        for (int i = 0; i < 4; i++) {
            float h = gelu_exact(acc[i][j] + bb);
            float y = Xs[(rg*4 + i)*XS_STRIDE + col] + h;
            acc[i][j] = y;
            sums[i] += y;
            sqs[i]  += y * y;
        }
    }
    #pragma unroll
    for (int i = 0; i < 4; i++) {
        #pragma unroll
        for (int off = 8; off > 0; off >>= 1) {
            sums[i] += __shfl_xor_sync(0xffffffffu, sums[i], off);
            sqs[i]  += __shfl_xor_sync(0xffffffffu, sqs[i],  off);
        }
    }
    #pragma unroll
    for (int i = 0; i < 4; i++) {
        float mu  = sums[i] * (1.f / DIM);
        float var = sqs[i] * (1.f / DIM) - mu * mu;
        float rs  = rsqrtf(var + EPS);
        int row = m0 + rg*4 + i;
        if (row < M) {
            #pragma unroll
            for (int j = 0; j < 8; j++) {
                int col = cg + 16*j;
                out[(size_t)row*DIM + col] =
                    (acc[i][j] - mu) * rs * lng[col] + lnb[col];
            }
        }
    }
}

// ---------------------------------------------------------------------------
extern "C" void kernel_launch(void* const* d_in, const int* in_sizes, int n_in,
                              void* d_out, int out_size)
{
    const float* x    = (const float*)d_in[0];
    const int*   ei   = (const int*)  d_in[1];
    const float* ew   = (const float*)d_in[2];
    const float* ef   = (const float*)d_in[3];
    // d_in[4] = batch (unused: single graph / LN is per-node anyway)
    const float* Wphi = (const float*)d_in[5];
    const float* bphi = (const float*)d_in[6];
    const float* Wg1  = (const float*)d_in[7];
    const float* bg1  = (const float*)d_in[8];
    const float* bng  = (const float*)d_in[9];
    const float* bnb  = (const float*)d_in[10];
    const float* bnm  = (const float*)d_in[11];
    const float* bnv  = (const float*)d_in[12];
    const float* Wg2  = (const float*)d_in[13];
    const float* bg2  = (const float*)d_in[14];
    const float* Wu   = (const float*)d_in[15];
    const float* bu   = (const float*)d_in[16];
    const float* lng  = (const float*)d_in[17];
    const float* lnb  = (const float*)d_in[18];
    float* out = (float*)d_out;

    int M = in_sizes[0] / DIM;
    int E = in_sizes[2];
    if (M > MAXN) return;

    cudaFuncSetAttribute(node_gemm,     cudaFuncAttributeMaxDynamicSharedMemorySize, SMEM_BYTES);
    cudaFuncSetAttribute(update_kernel, cudaFuncAttributeMaxDynamicSharedMemorySize, SMEM_BYTES);

    void* aggp = nullptr;
    cudaGetSymbolAddress(&aggp, g_agg);
    cudaMemsetAsync(aggp, 0, (size_t)M * DIM * sizeof(float), 0);

    param_kernel<<<1, DIM>>>(Wg1, bg1, bng, bnb, bnm, bnv);

    dim3 ggrid((M + BM - 1) / BM, 3);
    node_gemm<<<ggrid, 256, SMEM_BYTES>>>(x, Wphi, bphi, Wg1, bng, bnv, M);

    edge_kernel<<<2368, 256>>>(ei, ew, ef, Wg2, bg2, E);

    update_kernel<<<(M + BM - 1) / BM, 256, SMEM_BYTES>>>(x, Wu, bu, lng, lnb, out, M);
}

// round 2
// speedup vs baseline: 1.0814x; 1.0814x over previous
#include <cuda_runtime.h>
#include <math.h>

// ---------------------------------------------------------------------------
// EdgeGatedMPNNLayer — GB300 (sm_103a)  — Round 2
//  * GEMMs: thread owns 8 CONSECUTIVE cols -> Ws row via 2x LDS.128 (was 8 scalar)
//  * edge:  red.global.add.v4.f32 (1 RED per 4 floats), 2-edge unroll to overlap
//           LDG latency and the two shfl-reduce chains
// ---------------------------------------------------------------------------

#define DIM 128
#define MAXN 50000
#define EPS 1e-5f

#define BM 64
#define XS_STRIDE 132
#define SMEM_BYTES (DIM*DIM*4 + BM*XS_STRIDE*4)   // 99328 B -> 2 CTA/SM

__device__ float g_xj [MAXN*DIM];
__device__ float g_A  [MAXN*DIM];
__device__ float g_B  [MAXN*DIM];
__device__ float g_agg[MAXN*DIM];
__device__ float g_params[3*DIM];   // we0[128], we1[128], cbias[128]

__device__ __forceinline__ float gelu_exact(float v) {
    return 0.5f * v * (1.0f + erff(v * 0.70710678118654752f));
}

__device__ __forceinline__ void red_add_v4(float* p, float a, float b, float c, float d) {
    asm volatile("red.global.add.v4.f32 [%0], {%1,%2,%3,%4};"
                 :: "l"(p), "f"(a), "f"(b), "f"(c), "f"(d) : "memory");
}

// ---------------------------------------------------------------------------
__global__ void param_kernel(const float* __restrict__ Wg1, const float* __restrict__ bg1,
                             const float* __restrict__ bng, const float* __restrict__ bnb,
                             const float* __restrict__ bnm, const float* __restrict__ bnv)
{
    int n = threadIdx.x;
    if (n < DIM) {
        float s = bng[n] * rsqrtf(bnv[n] + EPS);
        g_params[n]         = Wg1[256*DIM + n] * s;
        g_params[DIM + n]   = Wg1[257*DIM + n] * s;
        g_params[2*DIM + n] = bg1[n]*s + (bnb[n] - bnm[n]*s);
    }
}

// ---------------------------------------------------------------------------
// Node GEMM: C[M,128] = X[M,128] @ W[128,128], per-column scale+bias epilogue.
// grid.y: 0 -> xj (bias b_phi), 1 -> A (BN scale), 2 -> B (BN scale)
// Block 256, tile 64x128. Thread (rg,cg): rows rg*4..+3, cols cg*8..+7.
// ---------------------------------------------------------------------------
__global__ void __launch_bounds__(256) node_gemm(
    const float* __restrict__ x,
    const float* __restrict__ Wphi, const float* __restrict__ bphi,
    const float* __restrict__ Wg1,
    const float* __restrict__ bng,  const float* __restrict__ bnv,
    int M)
{
    extern __shared__ float sm[];
    float* Ws = sm;               // [128][128]
    float* Xs = sm + DIM*DIM;     // [64][132]

    int mode = blockIdx.y;
    const float* W = (mode == 0) ? Wphi : (mode == 1 ? Wg1 : Wg1 + DIM*DIM);
    float* C       = (mode == 0) ? g_xj : (mode == 1 ? g_A : g_B);

    int m0 = blockIdx.x * BM;
    int t  = threadIdx.x;

    {
        const float4* Wv  = (const float4*)W;
        float4*       Wsv = (float4*)Ws;
        #pragma unroll
        for (int i = 0; i < 16; i++) Wsv[t + i*256] = Wv[t + i*256];
    }
    #pragma unroll
    for (int i = 0; i < 8; i++) {
        int idx = t + i*256;
        int row = idx >> 5;
        int c4  = idx & 31;
        float4 v = make_float4(0.f, 0.f, 0.f, 0.f);
        int grow = m0 + row;
        if (grow < M) v = ((const float4*)x)[(size_t)grow*32 + c4];
        *(float4*)(Xs + row*XS_STRIDE + c4*4) = v;
    }
    __syncthreads();

    int rg = t >> 4, cg = t & 15;
    int c0 = cg * 8;

    float acc[4][8];
    #pragma unroll
    for (int i = 0; i < 4; i++)
        #pragma unroll
        for (int j = 0; j < 8; j++) acc[i][j] = 0.f;

    #pragma unroll 8
    for (int k = 0; k < DIM; k++) {
        float4 w0 = *(const float4*)(Ws + k*DIM + c0);
        float4 w1 = *(const float4*)(Ws + k*DIM + c0 + 4);
        float xv[4];
        #pragma unroll
        for (int i = 0; i < 4; i++) xv[i] = Xs[(rg*4 + i)*XS_STRIDE + k];
        #pragma unroll
        for (int i = 0; i < 4; i++) {
            acc[i][0] = fmaf(xv[i], w0.x, acc[i][0]);
            acc[i][1] = fmaf(xv[i], w0.y, acc[i][1]);
            acc[i][2] = fmaf(xv[i], w0.z, acc[i][2]);
            acc[i][3] = fmaf(xv[i], w0.w, acc[i][3]);
            acc[i][4] = fmaf(xv[i], w1.x, acc[i][4]);
            acc[i][5] = fmaf(xv[i], w1.y, acc[i][5]);
            acc[i][6] = fmaf(xv[i], w1.z, acc[i][6]);
            acc[i][7] = fmaf(xv[i], w1.w, acc[i][7]);
        }
    }

    float sc[8], bs[8];
    #pragma unroll
    for (int j = 0; j < 8; j++) {
        int col = c0 + j;
        if (mode == 0) { sc[j] = 1.f; bs[j] = bphi[col]; }
        else           { sc[j] = bng[col] * rsqrtf(bnv[col] + EPS); bs[j] = 0.f; }
    }
    #pragma unroll
    for (int i = 0; i < 4; i++) {
        int row = m0 + rg*4 + i;
        if (row < M) {
            float4 v0, v1;
            v0.x = fmaf(acc[i][0], sc[0], bs[0]);
            v0.y = fmaf(acc[i][1], sc[1], bs[1]);
            v0.z = fmaf(acc[i][2], sc[2], bs[2]);
            v0.w = fmaf(acc[i][3], sc[3], bs[3]);
            v1.x = fmaf(acc[i][4], sc[4], bs[4]);
            v1.y = fmaf(acc[i][5], sc[5], bs[5]);
            v1.z = fmaf(acc[i][6], sc[6], bs[6]);
            v1.w = fmaf(acc[i][7], sc[7], bs[7]);
            *(float4*)(C + (size_t)row*DIM + c0)     = v0;
            *(float4*)(C + (size_t)row*DIM + c0 + 4) = v1;
        }
    }
}

// ---------------------------------------------------------------------------
// Edge kernel: warp per edge, 2-edge unroll; red.global.add.v4.f32 scatter.
// ---------------------------------------------------------------------------
__global__ void __launch_bounds__(256) edge_kernel(
    const int* __restrict__ ei, const float* __restrict__ ew,
    const float* __restrict__ ef, const float* __restrict__ Wg2,
    const float* __restrict__ bg2, int E)
{
    int lane = threadIdx.x & 31;
    int warp = (blockIdx.x * blockDim.x + threadIdx.x) >> 5;
    int nw   = (gridDim.x * blockDim.x) >> 5;

    float4 we0 = ((const float4*)(g_params          ))[lane];
    float4 we1 = ((const float4*)(g_params +     DIM))[lane];
    float4 cb  = ((const float4*)(g_params + 2 * DIM))[lane];
    float4 w2  = ((const float4*)Wg2)[lane];
    float  b2  = bg2[0];

    for (int e0 = warp*2; e0 < E; e0 += nw*2) {
        int e1 = e0 + 1;
        bool has1 = (e1 < E);

        int   src0 = ei[e0],       dst0 = ei[E + e0];
        int   src1 = has1 ? ei[e1] : src0;
        int   dst1 = has1 ? ei[E + e1] : dst0;
        float w_0  = ew[e0];
        float w_1  = has1 ? ew[e1] : 0.f;
        float2 ef0 = ((const float2*)ef)[e0];
        float2 ef1 = has1 ? ((const float2*)ef)[e1] : ef0;

        float4 a0 = __ldg(((const float4*)g_A)  + (size_t)dst0*32 + lane);
        float4 b0 = __ldg(((const float4*)g_B)  + (size_t)src0*32 + lane);
        float4 a1 = __ldg(((const float4*)g_A)  + (size_t)dst1*32 + lane);
        float4 b1 = __ldg(((const float4*)g_B)  + (size_t)src1*32 + lane);
        float4 x0 = __ldg(((const float4*)g_xj) + (size_t)src0*32 + lane);
        float4 x1 = __ldg(((const float4*)g_xj) + (size_t)src1*32 + lane);

        float4 h0, h1;
        h0.x = a0.x + b0.x + ef0.x*we0.x + ef0.y*we1.x + cb.x;
        h0.y = a0.y + b0.y + ef0.x*we0.y + ef0.y*we1.y + cb.y;
        h0.z = a0.z + b0.z + ef0.x*we0.z + ef0.y*we1.z + cb.z;
        h0.w = a0.w + b0.w + ef0.x*we0.w + ef0.y*we1.w + cb.w;
        h1.x = a1.x + b1.x + ef1.x*we0.x + ef1.y*we1.x + cb.x;
        h1.y = a1.y + b1.y + ef1.x*we0.y + ef1.y*we1.y + cb.y;
        h1.z = a1.z + b1.z + ef1.x*we0.z + ef1.y*we1.z + cb.z;
        h1.w = a1.w + b1.w + ef1.x*we0.w + ef1.y*we1.w + cb.w;

        float d0 = gelu_exact(h0.x)*w2.x + gelu_exact(h0.y)*w2.y
                 + gelu_exact(h0.z)*w2.z + gelu_exact(h0.w)*w2.w;
        float d1 = gelu_exact(h1.x)*w2.x + gelu_exact(h1.y)*w2.y
                 + gelu_exact(h1.z)*w2.z + gelu_exact(h1.w)*w2.w;

        #pragma unroll
        for (int off = 16; off > 0; off >>= 1) {
            d0 += __shfl_xor_sync(0xffffffffu, d0, off);
            d1 += __shfl_xor_sync(0xffffffffu, d1, off);
        }

        float c0 = w_0 / (1.f + __expf(-(d0 + b2)));
        float c1 = w_1 / (1.f + __expf(-(d1 + b2)));

        red_add_v4(g_agg + (size_t)dst0*DIM + lane*4,
                   x0.x*c0, x0.y*c0, x0.z*c0, x0.w*c0);
        if (has1)
            red_add_v4(g_agg + (size_t)dst1*DIM + lane*4,
                       x1.x*c1, x1.y*c1, x1.z*c1, x1.w*c1);
    }
}

// ---------------------------------------------------------------------------
// Update GEMM + fused epilogue (agg phase first, x phase last so Xs holds x):
//   h = gelu(x@Wu[:128] + agg@Wu[128:] + b_u); y = x + h; out = LN(y)
// ---------------------------------------------------------------------------
__global__ void __launch_bounds__(256) update_kernel(
    const float* __restrict__ x, const float* __restrict__ Wu,
    const float* __restrict__ bu,
    const float* __restrict__ lng, const float* __restrict__ lnb,
    float* __restrict__ out, int M)
{
    extern __shared__ float sm[];
    float* Ws = sm;
    float* Xs = sm + DIM*DIM;

    int m0 = blockIdx.x * BM;
    int t  = threadIdx.x;
    int rg = t >> 4, cg = t & 15;
    int c0 = cg * 8;

    float acc[4][8];
    #pragma unroll
    for (int i = 0; i < 4; i++)
        #pragma unroll
        for (int j = 0; j < 8; j++) acc[i][j] = 0.f;

    #pragma unroll
    for (int p = 0; p < 2; p++) {
        const float* src = (p == 0) ? (const float*)g_agg : x;
        const float* W   = Wu + ((p == 0) ? DIM*DIM : 0);
        if (p) __syncthreads();

        {
            const float4* Wv  = (const float4*)W;
            float4*       Wsv = (float4*)Ws;
            #pragma unroll
            for (int i = 0; i < 16; i++) Wsv[t + i*256] = Wv[t + i*256];
        }
        #pragma unroll
        for (int i = 0; i < 8; i++) {
            int idx = t + i*256;
            int row = idx >> 5;
            int c4  = idx & 31;
            float4 v = make_float4(0.f, 0.f, 0.f, 0.f);
            int grow = m0 + row;
            if (grow < M) v = ((const float4*)src)[(size_t)grow*32 + c4];
            *(float4*)(Xs + row*XS_STRIDE + c4*4) = v;
        }
        __syncthreads();

        #pragma unroll 8
        for (int k = 0; k < DIM; k++) {
            float4 w0 = *(const float4*)(Ws + k*DIM + c0);
            float4 w1 = *(const float4*)(Ws + k*DIM + c0 + 4);
            float xv[4];
            #pragma unroll
            for (int i = 0; i < 4; i++) xv[i] = Xs[(rg*4 + i)*XS_STRIDE + k];
            #pragma unroll
            for (int i = 0; i < 4; i++) {
                acc[i][0] = fmaf(xv[i], w0.x, acc[i][0]);
                acc[i][1] = fmaf(xv[i], w0.y, acc[i][1]);
                acc[i][2] = fmaf(xv[i], w0.z, acc[i][2]);
                acc[i][3] = fmaf(xv[i], w0.w, acc[i][3]);
                acc[i][4] = fmaf(xv[i], w1.x, acc[i][4]);
                acc[i][5] = fmaf(xv[i], w1.y, acc[i][5]);
                acc[i][6] = fmaf(xv[i], w1.z, acc[i][6]);
                acc[i][7] = fmaf(xv[i], w1.w, acc[i][7]);
            }
        }
    }

    // epilogue: Xs holds the x tile. y = x + gelu(acc + bu), then LN per row.
    float bb[8];
    #pragma unroll
    for (int j = 0; j < 8; j++) bb[j] = bu[c0 + j];

    float sums[4] = {0.f, 0.f, 0.f, 0.f};
    float sqs [4] = {0.f, 0.f, 0.f, 0.f};
    #pragma unroll
    for (int i = 0; i < 4; i++) {
        float4 xa = *(const float4*)(Xs + (rg*4 + i)*XS_STRIDE + c0);
        float4 xb = *(const float4*)(Xs + (rg*4 + i)*XS_STRIDE + c0 + 4);
        float xr[8] = {xa.x, xa.y, xa.z, xa.w, xb.x, xb.y, xb.z, xb.w};
        #pragma unroll
        for (int j = 0; j < 8; j++) {
            float y = xr[j] + gelu_exact(acc[i][j] + bb[j]);
            acc[i][j] = y;
            sums[i] += y;
            sqs[i]  += y * y;
        }
    }
    #pragma unroll
    for (int i = 0; i < 4; i++) {
        #pragma unroll
        for (int off = 8; off > 0; off >>= 1) {
            sums[i] += __shfl_xor_sync(0xffffffffu, sums[i], off);
            sqs[i]  += __shfl_xor_sync(0xffffffffu, sqs[i],  off);
        }
    }
    float lg[8], lb[8];
    #pragma unroll
    for (int j = 0; j < 8; j++) { lg[j] = lng[c0 + j]; lb[j] = lnb[c0 + j]; }

    #pragma unroll
    for (int i = 0; i < 4; i++) {
        float mu  = sums[i] * (1.f / DIM);
        float var = sqs[i] * (1.f / DIM) - mu * mu;
        float rs  = rsqrtf(var + EPS);
        int row = m0 + rg*4 + i;
        if (row < M) {
            float4 v0, v1;
            v0.x = (acc[i][0] - mu) * rs * lg[0] + lb[0];
            v0.y = (acc[i][1] - mu) * rs * lg[1] + lb[1];
            v0.z = (acc[i][2] - mu) * rs * lg[2] + lb[2];
            v0.w = (acc[i][3] - mu) * rs * lg[3] + lb[3];
            v1.x = (acc[i][4] - mu) * rs * lg[4] + lb[4];
            v1.y = (acc[i][5] - mu) * rs * lg[5] + lb[5];
            v1.z = (acc[i][6] - mu) * rs * lg[6] + lb[6];
            v1.w = (acc[i][7] - mu) * rs * lg[7] + lb[7];
            *(float4*)(out + (size_t)row*DIM + c0)     = v0;
            *(float4*)(out + (size_t)row*DIM + c0 + 4) = v1;
        }
    }
}

// ---------------------------------------------------------------------------
extern "C" void kernel_launch(void* const* d_in, const int* in_sizes, int n_in,
                              void* d_out, int out_size)
{
    const float* x    = (const float*)d_in[0];
    const int*   ei   = (const int*)  d_in[1];
    const float* ew   = (const float*)d_in[2];
    const float* ef   = (const float*)d_in[3];
    const float* Wphi = (const float*)d_in[5];
    const float* bphi = (const float*)d_in[6];
    const float* Wg1  = (const float*)d_in[7];
    const float* bg1  = (const float*)d_in[8];
    const float* bng  = (const float*)d_in[9];
    const float* bnb  = (const float*)d_in[10];
    const float* bnm  = (const float*)d_in[11];
    const float* bnv  = (const float*)d_in[12];
    const float* Wg2  = (const float*)d_in[13];
    const float* bg2  = (const float*)d_in[14];
    const float* Wu   = (const float*)d_in[15];
    const float* bu   = (const float*)d_in[16];
    const float* lng  = (const float*)d_in[17];
    const float* lnb  = (const float*)d_in[18];
    float* out = (float*)d_out;

    int M = in_sizes[0] / DIM;
    int E = in_sizes[2];
    if (M > MAXN) return;

    cudaFuncSetAttribute(node_gemm,     cudaFuncAttributeMaxDynamicSharedMemorySize, SMEM_BYTES);
    cudaFuncSetAttribute(update_kernel, cudaFuncAttributeMaxDynamicSharedMemorySize, SMEM_BYTES);

    void* aggp = nullptr;
    cudaGetSymbolAddress(&aggp, g_agg);
    cudaMemsetAsync(aggp, 0, (size_t)M * DIM * sizeof(float), 0);

    param_kernel<<<1, DIM>>>(Wg1, bg1, bng, bnb, bnm, bnv);

    dim3 ggrid((M + BM - 1) / BM, 3);
    node_gemm<<<ggrid, 256, SMEM_BYTES>>>(x, Wphi, bphi, Wg1, bng, bnv, M);

    edge_kernel<<<2368, 256>>>(ei, ew, ef, Wg2, bg2, E);

    update_kernel<<<(M + BM - 1) / BM, 256, SMEM_BYTES>>>(x, Wu, bu, lng, lnb, out, M);
}

// round 3
// speedup vs baseline: 1.3880x; 1.2835x over previous
#include <cuda_runtime.h>
#include <math.h>

// ---------------------------------------------------------------------------
// EdgeGatedMPNNLayer — GB300 (sm_103a)  — Round 3
//  * GEMM mapping fixed: thread cols = lane*4 (conflict-free LDS.128 on W),
//    thread rows = warp*8 (X reads are broadcast float4). acc[8][4].
//  * 3 node GEMMs fused into one kernel (X tile staged once).
//  * edge kernel unchanged (RED.v4 + 2-edge unroll) — it was the R2 win.
// ---------------------------------------------------------------------------

#define DIM 128
#define MAXN 50000
#define EPS 1e-5f

#define BM 64
#define XSTR 128
#define SMEM_BYTES ((DIM*DIM + BM*XSTR)*4)   // 64KB + 32KB = 96KB -> 2 CTA/SM

__device__ float g_xj [MAXN*DIM];
__device__ float g_A  [MAXN*DIM];
__device__ float g_B  [MAXN*DIM];
__device__ float g_agg[MAXN*DIM];
__device__ float g_params[3*DIM];   // we0[128], we1[128], cbias[128]

__device__ __forceinline__ float gelu_exact(float v) {
    return 0.5f * v * (1.0f + erff(v * 0.70710678118654752f));
}

__device__ __forceinline__ void red_add_v4(float* p, float a, float b, float c, float d) {
    asm volatile("red.global.add.v4.f32 [%0], {%1,%2,%3,%4};"
                 :: "l"(p), "f"(a), "f"(b), "f"(c), "f"(d) : "memory");
}

// ---------------------------------------------------------------------------
// GEMM core: acc[8][4] += Xs[r0+i][:] * Ws[:][lane*4+j]
// Ws row read: LDS.128 lane*4 -> conflict-free. Xs read: broadcast float4.
// ---------------------------------------------------------------------------
__device__ __forceinline__ void gemm_core(const float* __restrict__ Ws,
                                          const float* __restrict__ Xs,
                                          int lane, int r0, float acc[8][4])
{
    #pragma unroll 2
    for (int k4 = 0; k4 < 32; k4++) {
        float4 w[4];
        #pragma unroll
        for (int kk = 0; kk < 4; kk++)
            w[kk] = *(const float4*)(Ws + (k4*4 + kk)*DIM + lane*4);
        #pragma unroll
        for (int i = 0; i < 8; i++) {
            float4 xq = *(const float4*)(Xs + (r0 + i)*XSTR + k4*4);
            float xr[4] = {xq.x, xq.y, xq.z, xq.w};
            #pragma unroll
            for (int kk = 0; kk < 4; kk++) {
                acc[i][0] = fmaf(xr[kk], w[kk].x, acc[i][0]);
                acc[i][1] = fmaf(xr[kk], w[kk].y, acc[i][1]);
                acc[i][2] = fmaf(xr[kk], w[kk].z, acc[i][2]);
                acc[i][3] = fmaf(xr[kk], w[kk].w, acc[i][3]);
            }
        }
    }
}

__device__ __forceinline__ void load_W_tile(float* Ws, const float* __restrict__ W, int t)
{
    const float4* Wv  = (const float4*)W;
    float4*       Wsv = (float4*)Ws;
    #pragma unroll
    for (int i = 0; i < 16; i++) Wsv[t + i*256] = Wv[t + i*256];
}

__device__ __forceinline__ void load_X_tile(float* Xs, const float* __restrict__ src,
                                            int t, int m0, int M)
{
    #pragma unroll
    for (int i = 0; i < 8; i++) {
        int idx = t + i*256;               // float4 index; row = idx>>5 (XSTR==DIM)
        int grow = m0 + (idx >> 5);
        float4 v = make_float4(0.f, 0.f, 0.f, 0.f);
        if (grow < M) v = ((const float4*)src)[(size_t)m0*32 + idx];
        ((float4*)Xs)[idx] = v;
    }
}

// ---------------------------------------------------------------------------
__global__ void param_kernel(const float* __restrict__ Wg1, const float* __restrict__ bg1,
                             const float* __restrict__ bng, const float* __restrict__ bnb,
                             const float* __restrict__ bnm, const float* __restrict__ bnv)
{
    int n = threadIdx.x;
    if (n < DIM) {
        float s = bng[n] * rsqrtf(bnv[n] + EPS);
        g_params[n]         = Wg1[256*DIM + n] * s;
        g_params[DIM + n]   = Wg1[257*DIM + n] * s;
        g_params[2*DIM + n] = bg1[n]*s + (bnb[n] - bnm[n]*s);
    }
}

// ---------------------------------------------------------------------------
// Fused node GEMMs: xj = x@Wphi + bphi; A = (x@Wg1[:128]) * s; B = (x@Wg1[128:]) * s
// X tile staged once; loop over the 3 weight matrices.
// ---------------------------------------------------------------------------
__global__ void __launch_bounds__(256, 2) node_fused(
    const float* __restrict__ x,
    const float* __restrict__ Wphi, const float* __restrict__ bphi,
    const float* __restrict__ Wg1,
    const float* __restrict__ bng,  const float* __restrict__ bnv,
    int M)
{
    extern __shared__ float sm[];
    float* Ws = sm;
    float* Xs = sm + DIM*DIM;

    int t = threadIdx.x, lane = t & 31, warp = t >> 5;
    int m0 = blockIdx.x * BM, r0 = warp * 8;
    int c0 = lane * 4;

    load_X_tile(Xs, x, t, m0, M);

    float4 g4 = *(const float4*)(bng + c0);
    float4 v4 = *(const float4*)(bnv + c0);
    float4 bnsc;
    bnsc.x = g4.x * rsqrtf(v4.x + EPS);
    bnsc.y = g4.y * rsqrtf(v4.y + EPS);
    bnsc.z = g4.z * rsqrtf(v4.z + EPS);
    bnsc.w = g4.w * rsqrtf(v4.w + EPS);
    float4 bp = *(const float4*)(bphi + c0);

    #pragma unroll 1
    for (int mode = 0; mode < 3; mode++) {
        const float* W = (mode == 0) ? Wphi : (mode == 1 ? Wg1 : Wg1 + DIM*DIM);
        float* C       = (mode == 0) ? g_xj : (mode == 1 ? g_A : g_B);

        __syncthreads();                 // Xs ready / previous compute done
        load_W_tile(Ws, W, t);
        __syncthreads();

        float acc[8][4];
        #pragma unroll
        for (int i = 0; i < 8; i++)
            #pragma unroll
            for (int j = 0; j < 4; j++) acc[i][j] = 0.f;

        gemm_core(Ws, Xs, lane, r0, acc);

        float4 sc = (mode == 0) ? make_float4(1.f,1.f,1.f,1.f) : bnsc;
        float4 bs = (mode == 0) ? bp : make_float4(0.f,0.f,0.f,0.f);

        #pragma unroll
        for (int i = 0; i < 8; i++) {
            int row = m0 + r0 + i;
            if (row < M) {
                float4 v;
                v.x = fmaf(acc[i][0], sc.x, bs.x);
                v.y = fmaf(acc[i][1], sc.y, bs.y);
                v.z = fmaf(acc[i][2], sc.z, bs.z);
                v.w = fmaf(acc[i][3], sc.w, bs.w);
                ((float4*)C)[(size_t)row*32 + lane] = v;
            }
        }
    }
}

// ---------------------------------------------------------------------------
// Edge kernel: warp per edge, 2-edge unroll; red.global.add.v4.f32 scatter.
// ---------------------------------------------------------------------------
__global__ void __launch_bounds__(256) edge_kernel(
    const int* __restrict__ ei, const float* __restrict__ ew,
    const float* __restrict__ ef, const float* __restrict__ Wg2,
    const float* __restrict__ bg2, int E)
{
    int lane = threadIdx.x & 31;
    int warp = (blockIdx.x * blockDim.x + threadIdx.x) >> 5;
    int nw   = (gridDim.x * blockDim.x) >> 5;

    float4 we0 = ((const float4*)(g_params          ))[lane];
    float4 we1 = ((const float4*)(g_params +     DIM))[lane];
    float4 cb  = ((const float4*)(g_params + 2 * DIM))[lane];
    float4 w2  = ((const float4*)Wg2)[lane];
    float  b2  = bg2[0];

    for (int e0 = warp*2; e0 < E; e0 += nw*2) {
        int e1 = e0 + 1;
        bool has1 = (e1 < E);

        int   src0 = ei[e0],       dst0 = ei[E + e0];
        int   src1 = has1 ? ei[e1] : src0;
        int   dst1 = has1 ? ei[E + e1] : dst0;
        float w_0  = ew[e0];
        float w_1  = has1 ? ew[e1] : 0.f;
        float2 ef0 = ((const float2*)ef)[e0];
        float2 ef1 = has1 ? ((const float2*)ef)[e1] : ef0;

        float4 a0 = __ldg(((const float4*)g_A)  + (size_t)dst0*32 + lane);
        float4 b0 = __ldg(((const float4*)g_B)  + (size_t)src0*32 + lane);
        float4 a1 = __ldg(((const float4*)g_A)  + (size_t)dst1*32 + lane);
        float4 b1 = __ldg(((const float4*)g_B)  + (size_t)src1*32 + lane);
        float4 x0 = __ldg(((const float4*)g_xj) + (size_t)src0*32 + lane);
        float4 x1 = __ldg(((const float4*)g_xj) + (size_t)src1*32 + lane);

        float4 h0, h1;
        h0.x = a0.x + b0.x + ef0.x*we0.x + ef0.y*we1.x + cb.x;
        h0.y = a0.y + b0.y + ef0.x*we0.y + ef0.y*we1.y + cb.y;
        h0.z = a0.z + b0.z + ef0.x*we0.z + ef0.y*we1.z + cb.z;
        h0.w = a0.w + b0.w + ef0.x*we0.w + ef0.y*we1.w + cb.w;
        h1.x = a1.x + b1.x + ef1.x*we0.x + ef1.y*we1.x + cb.x;
        h1.y = a1.y + b1.y + ef1.x*we0.y + ef1.y*we1.y + cb.y;
        h1.z = a1.z + b1.z + ef1.x*we0.z + ef1.y*we1.z + cb.z;
        h1.w = a1.w + b1.w + ef1.x*we0.w + ef1.y*we1.w + cb.w;

        float d0 = gelu_exact(h0.x)*w2.x + gelu_exact(h0.y)*w2.y
                 + gelu_exact(h0.z)*w2.z + gelu_exact(h0.w)*w2.w;
        float d1 = gelu_exact(h1.x)*w2.x + gelu_exact(h1.y)*w2.y
                 + gelu_exact(h1.z)*w2.z + gelu_exact(h1.w)*w2.w;

        #pragma unroll
        for (int off = 16; off > 0; off >>= 1) {
            d0 += __shfl_xor_sync(0xffffffffu, d0, off);
            d1 += __shfl_xor_sync(0xffffffffu, d1, off);
        }

        float c0 = w_0 / (1.f + __expf(-(d0 + b2)));
        float c1 = w_1 / (1.f + __expf(-(d1 + b2)));

        red_add_v4(g_agg + (size_t)dst0*DIM + lane*4,
                   x0.x*c0, x0.y*c0, x0.z*c0, x0.w*c0);
        if (has1)
            red_add_v4(g_agg + (size_t)dst1*DIM + lane*4,
                       x1.x*c1, x1.y*c1, x1.z*c1, x1.w*c1);
    }
}

// ---------------------------------------------------------------------------
// Update GEMM + fused epilogue (agg phase first, x phase last so Xs holds x):
//   h = gelu(x@Wu[:128] + agg@Wu[128:] + b_u); y = x + h; out = LN(y)
// ---------------------------------------------------------------------------
__global__ void __launch_bounds__(256, 2) update_kernel(
    const float* __restrict__ x, const float* __restrict__ Wu,
    const float* __restrict__ bu,
    const float* __restrict__ lng, const float* __restrict__ lnb,
    float* __restrict__ out, int M)
{
    extern __shared__ float sm[];
    float* Ws = sm;
    float* Xs = sm + DIM*DIM;

    int t = threadIdx.x, lane = t & 31, warp = t >> 5;
    int m0 = blockIdx.x * BM, r0 = warp * 8;
    int c0 = lane * 4;

    float acc[8][4];
    #pragma unroll
    for (int i = 0; i < 8; i++)
        #pragma unroll
        for (int j = 0; j < 4; j++) acc[i][j] = 0.f;

    #pragma unroll 1
    for (int p = 0; p < 2; p++) {
        const float* src = (p == 0) ? (const float*)g_agg : x;
        const float* W   = Wu + ((p == 0) ? DIM*DIM : 0);

        if (p) __syncthreads();          // previous compute done before overwrite
        load_W_tile(Ws, W, t);
        load_X_tile(Xs, src, t, m0, M);
        __syncthreads();

        gemm_core(Ws, Xs, lane, r0, acc);
    }

    // epilogue: Xs holds the x tile. y = x + gelu(acc + bu), then LN per row.
    float4 bb = *(const float4*)(bu + c0);
    float sums[8], sqs[8];

    #pragma unroll
    for (int i = 0; i < 8; i++) {
        float4 xv = *(const float4*)(Xs + (r0 + i)*XSTR + c0);
        float y0 = xv.x + gelu_exact(acc[i][0] + bb.x);
        float y1 = xv.y + gelu_exact(acc[i][1] + bb.y);
        float y2 = xv.z + gelu_exact(acc[i][2] + bb.z);
        float y3 = xv.w + gelu_exact(acc[i][3] + bb.w);
        acc[i][0] = y0; acc[i][1] = y1; acc[i][2] = y2; acc[i][3] = y3;
        sums[i] = y0 + y1 + y2 + y3;
        sqs[i]  = y0*y0 + y1*y1 + y2*y2 + y3*y3;
    }
    #pragma unroll
    for (int off = 16; off > 0; off >>= 1) {
        #pragma unroll
        for (int i = 0; i < 8; i++) {
            sums[i] += __shfl_xor_sync(0xffffffffu, sums[i], off);
            sqs[i]  += __shfl_xor_sync(0xffffffffu, sqs[i],  off);
        }
    }
    float4 lg = *(const float4*)(lng + c0);
    float4 lb = *(const float4*)(lnb + c0);

    #pragma unroll
    for (int i = 0; i < 8; i++) {
        float mu  = sums[i] * (1.f / DIM);
        float var = sqs[i] * (1.f / DIM) - mu * mu;
        float rs  = rsqrtf(var + EPS);
        int row = m0 + r0 + i;
        if (row < M) {
            float4 v;
            v.x = (acc[i][0] - mu) * rs * lg.x + lb.x;
            v.y = (acc[i][1] - mu) * rs * lg.y + lb.y;
            v.z = (acc[i][2] - mu) * rs * lg.z + lb.z;
            v.w = (acc[i][3] - mu) * rs * lg.w + lb.w;
            ((float4*)out)[(size_t)row*32 + lane] = v;
        }
    }
}

// ---------------------------------------------------------------------------
extern "C" void kernel_launch(void* const* d_in, const int* in_sizes, int n_in,
                              void* d_out, int out_size)
{
    const float* x    = (const float*)d_in[0];
    const int*   ei   = (const int*)  d_in[1];
    const float* ew   = (const float*)d_in[2];
    const float* ef   = (const float*)d_in[3];
    const float* Wphi = (const float*)d_in[5];
    const float* bphi = (const float*)d_in[6];
    const float* Wg1  = (const float*)d_in[7];
    const float* bg1  = (const float*)d_in[8];
    const float* bng  = (const float*)d_in[9];
    const float* bnb  = (const float*)d_in[10];
    const float* bnm  = (const float*)d_in[11];
    const float* bnv  = (const float*)d_in[12];
    const float* Wg2  = (const float*)d_in[13];
    const float* bg2  = (const float*)d_in[14];
    const float* Wu   = (const float*)d_in[15];
    const float* bu   = (const float*)d_in[16];
    const float* lng  = (const float*)d_in[17];
    const float* lnb  = (const float*)d_in[18];
    float* out = (float*)d_out;

    int M = in_sizes[0] / DIM;
    int E = in_sizes[2];
    if (M > MAXN) return;

    cudaFuncSetAttribute(node_fused,    cudaFuncAttributeMaxDynamicSharedMemorySize, SMEM_BYTES);
    cudaFuncSetAttribute(update_kernel, cudaFuncAttributeMaxDynamicSharedMemorySize, SMEM_BYTES);

    void* aggp = nullptr;
    cudaGetSymbolAddress(&aggp, g_agg);
    cudaMemsetAsync(aggp, 0, (size_t)M * DIM * sizeof(float), 0);

    param_kernel<<<1, DIM>>>(Wg1, bg1, bng, bnb, bnm, bnv);

    node_fused<<<(M + BM - 1) / BM, 256, SMEM_BYTES>>>(x, Wphi, bphi, Wg1, bng, bnv, M);

    edge_kernel<<<2368, 256>>>(ei, ew, ef, Wg2, bg2, E);

    update_kernel<<<(M + BM - 1) / BM, 256, SMEM_BYTES>>>(x, Wu, bu, lng, lnb, out, M);
}

// round 4
// speedup vs baseline: 1.4037x; 1.0114x over previous
#include <cuda_runtime.h>
#include <math.h>

// ---------------------------------------------------------------------------
// EdgeGatedMPNNLayer — GB300 (sm_103a)  — Round 4
//  * GEMM inner loop rewritten with packed fma.rn.f32x2 (FFMA2): halves the
//    fma-pipe work; x broadcast duplicated via mov.b64 (alu pipe, idle).
//  * Everything else as R3 (conflict-free LDS mapping, fused node GEMMs,
//    RED.v4 edge scatter).
// ---------------------------------------------------------------------------

#define DIM 128
#define MAXN 50000
#define EPS 1e-5f

#define BM 64
#define XSTR 128
#define SMEM_BYTES ((DIM*DIM + BM*XSTR)*4)   // 96KB -> 2 CTA/SM

typedef unsigned long long u64;

__device__ float g_xj [MAXN*DIM];
__device__ float g_A  [MAXN*DIM];
__device__ float g_B  [MAXN*DIM];
__device__ float g_agg[MAXN*DIM];
__device__ float g_params[3*DIM];   // we0[128], we1[128], cbias[128]

__device__ __forceinline__ float gelu_exact(float v) {
    return 0.5f * v * (1.0f + erff(v * 0.70710678118654752f));
}

__device__ __forceinline__ void red_add_v4(float* p, float a, float b, float c, float d) {
    asm volatile("red.global.add.v4.f32 [%0], {%1,%2,%3,%4};"
                 :: "l"(p), "f"(a), "f"(b), "f"(c), "f"(d) : "memory");
}

__device__ __forceinline__ u64 pack2(float a, float b) {
    u64 r; asm("mov.b64 %0, {%1, %2};" : "=l"(r) : "f"(a), "f"(b)); return r;
}
__device__ __forceinline__ void fma2(u64& d, u64 a, u64 b) {
    asm("fma.rn.f32x2 %0, %1, %2, %0;" : "+l"(d) : "l"(a), "l"(b));
}
__device__ __forceinline__ float2 unpack2(u64 v) {
    float2 r; asm("mov.b64 {%0, %1}, %2;" : "=f"(r.x), "=f"(r.y) : "l"(v)); return r;
}

// ---------------------------------------------------------------------------
// GEMM core (FFMA2): acc[i] = packed pairs of cols (lane*4+0,1) and (+2,3).
// W row pairs come directly from LDS.128 (ulonglong2); x broadcast duplicated.
// ---------------------------------------------------------------------------
__device__ __forceinline__ void gemm_core(const float* __restrict__ Ws,
                                          const float* __restrict__ Xs,
                                          int lane, int r0, u64 acc[8][2])
{
    #pragma unroll 2
    for (int k4 = 0; k4 < 32; k4++) {
        u64 w[4][2];
        #pragma unroll
        for (int kk = 0; kk < 4; kk++) {
            ulonglong2 wv = *(const ulonglong2*)(Ws + (k4*4 + kk)*DIM + lane*4);
            w[kk][0] = wv.x; w[kk][1] = wv.y;
        }
        #pragma unroll
        for (int i = 0; i < 8; i++) {
            float4 xq = *(const float4*)(Xs + (r0 + i)*XSTR + k4*4);
            u64 x0 = pack2(xq.x, xq.x);
            u64 x1 = pack2(xq.y, xq.y);
            u64 x2 = pack2(xq.z, xq.z);
            u64 x3 = pack2(xq.w, xq.w);
            fma2(acc[i][0], x0, w[0][0]); fma2(acc[i][1], x0, w[0][1]);
            fma2(acc[i][0], x1, w[1][0]); fma2(acc[i][1], x1, w[1][1]);
            fma2(acc[i][0], x2, w[2][0]); fma2(acc[i][1], x2, w[2][1]);
            fma2(acc[i][0], x3, w[3][0]); fma2(acc[i][1], x3, w[3][1]);
        }
    }
}

__device__ __forceinline__ void load_W_tile(float* Ws, const float* __restrict__ W, int t)
{
    const float4* Wv  = (const float4*)W;
    float4*       Wsv = (float4*)Ws;
    #pragma unroll
    for (int i = 0; i < 16; i++) Wsv[t + i*256] = Wv[t + i*256];
}

__device__ __forceinline__ void load_X_tile(float* Xs, const float* __restrict__ src,
                                            int t, int m0, int M)
{
    #pragma unroll
    for (int i = 0; i < 8; i++) {
        int idx = t + i*256;               // float4 index; row = idx>>5 (XSTR==DIM)
        int grow = m0 + (idx >> 5);
        float4 v = make_float4(0.f, 0.f, 0.f, 0.f);
        if (grow < M) v = ((const float4*)src)[(size_t)m0*32 + idx];
        ((float4*)Xs)[idx] = v;
    }
}

// ---------------------------------------------------------------------------
__global__ void param_kernel(const float* __restrict__ Wg1, const float* __restrict__ bg1,
                             const float* __restrict__ bng, const float* __restrict__ bnb,
                             const float* __restrict__ bnm, const float* __restrict__ bnv)
{
    int n = threadIdx.x;
    if (n < DIM) {
        float s = bng[n] * rsqrtf(bnv[n] + EPS);
        g_params[n]         = Wg1[256*DIM + n] * s;
        g_params[DIM + n]   = Wg1[257*DIM + n] * s;
        g_params[2*DIM + n] = bg1[n]*s + (bnb[n] - bnm[n]*s);
    }
}

// ---------------------------------------------------------------------------
// Fused node GEMMs: xj = x@Wphi + bphi; A = (x@Wg1[:128]) * s; B = (x@Wg1[128:]) * s
// ---------------------------------------------------------------------------
__global__ void __launch_bounds__(256, 2) node_fused(
    const float* __restrict__ x,
    const float* __restrict__ Wphi, const float* __restrict__ bphi,
    const float* __restrict__ Wg1,
    const float* __restrict__ bng,  const float* __restrict__ bnv,
    int M)
{
    extern __shared__ float sm[];
    float* Ws = sm;
    float* Xs = sm + DIM*DIM;

    int t = threadIdx.x, lane = t & 31, warp = t >> 5;
    int m0 = blockIdx.x * BM, r0 = warp * 8;
    int c0 = lane * 4;

    load_X_tile(Xs, x, t, m0, M);

    float4 g4 = *(const float4*)(bng + c0);
    float4 v4 = *(const float4*)(bnv + c0);
    float bnsc[4];
    bnsc[0] = g4.x * rsqrtf(v4.x + EPS);
    bnsc[1] = g4.y * rsqrtf(v4.y + EPS);
    bnsc[2] = g4.z * rsqrtf(v4.z + EPS);
    bnsc[3] = g4.w * rsqrtf(v4.w + EPS);
    float4 bp = *(const float4*)(bphi + c0);

    #pragma unroll 1
    for (int mode = 0; mode < 3; mode++) {
        const float* W = (mode == 0) ? Wphi : (mode == 1 ? Wg1 : Wg1 + DIM*DIM);
        float* C       = (mode == 0) ? g_xj : (mode == 1 ? g_A : g_B);

        __syncthreads();                 // Xs ready / previous compute done
        load_W_tile(Ws, W, t);
        __syncthreads();

        u64 acc[8][2];
        #pragma unroll
        for (int i = 0; i < 8; i++) { acc[i][0] = 0ull; acc[i][1] = 0ull; }

        gemm_core(Ws, Xs, lane, r0, acc);

        float sc[4] = {1.f, 1.f, 1.f, 1.f};
        float bs[4] = {bp.x, bp.y, bp.z, bp.w};
        if (mode != 0) {
            sc[0] = bnsc[0]; sc[1] = bnsc[1]; sc[2] = bnsc[2]; sc[3] = bnsc[3];
            bs[0] = bs[1] = bs[2] = bs[3] = 0.f;
        }

        #pragma unroll
        for (int i = 0; i < 8; i++) {
            int row = m0 + r0 + i;
            if (row < M) {
                float2 p0 = unpack2(acc[i][0]);
                float2 p1 = unpack2(acc[i][1]);
                float4 v;
                v.x = fmaf(p0.x, sc[0], bs[0]);
                v.y = fmaf(p0.y, sc[1], bs[1]);
                v.z = fmaf(p1.x, sc[2], bs[2]);
                v.w = fmaf(p1.y, sc[3], bs[3]);
                ((float4*)C)[(size_t)row*32 + lane] = v;
            }
        }
    }
}

// ---------------------------------------------------------------------------
// Edge kernel: warp per edge, 2-edge unroll; red.global.add.v4.f32 scatter.
// ---------------------------------------------------------------------------
__global__ void __launch_bounds__(256) edge_kernel(
    const int* __restrict__ ei, const float* __restrict__ ew,
    const float* __restrict__ ef, const float* __restrict__ Wg2,
    const float* __restrict__ bg2, int E)
{
    int lane = threadIdx.x & 31;
    int warp = (blockIdx.x * blockDim.x + threadIdx.x) >> 5;
    int nw   = (gridDim.x * blockDim.x) >> 5;

    float4 we0 = ((const float4*)(g_params          ))[lane];
    float4 we1 = ((const float4*)(g_params +     DIM))[lane];
    float4 cb  = ((const float4*)(g_params + 2 * DIM))[lane];
    float4 w2  = ((const float4*)Wg2)[lane];
    float  b2  = bg2[0];

    for (int e0 = warp*2; e0 < E; e0 += nw*2) {
        int e1 = e0 + 1;
        bool has1 = (e1 < E);

        int   src0 = ei[e0],       dst0 = ei[E + e0];
        int   src1 = has1 ? ei[e1] : src0;
        int   dst1 = has1 ? ei[E + e1] : dst0;
        float w_0  = ew[e0];
        float w_1  = has1 ? ew[e1] : 0.f;
        float2 ef0 = ((const float2*)ef)[e0];
        float2 ef1 = has1 ? ((const float2*)ef)[e1] : ef0;

        float4 a0 = __ldg(((const float4*)g_A)  + (size_t)dst0*32 + lane);
        float4 b0 = __ldg(((const float4*)g_B)  + (size_t)src0*32 + lane);
        float4 a1 = __ldg(((const float4*)g_A)  + (size_t)dst1*32 + lane);
        float4 b1 = __ldg(((const float4*)g_B)  + (size_t)src1*32 + lane);
        float4 x0 = __ldg(((const float4*)g_xj) + (size_t)src0*32 + lane);
        float4 x1 = __ldg(((const float4*)g_xj) + (size_t)src1*32 + lane);

        float4 h0, h1;
        h0.x = a0.x + b0.x + ef0.x*we0.x + ef0.y*we1.x + cb.x;
        h0.y = a0.y + b0.y + ef0.x*we0.y + ef0.y*we1.y + cb.y;
        h0.z = a0.z + b0.z + ef0.x*we0.z + ef0.y*we1.z + cb.z;
        h0.w = a0.w + b0.w + ef0.x*we0.w + ef0.y*we1.w + cb.w;
        h1.x = a1.x + b1.x + ef1.x*we0.x + ef1.y*we1.x + cb.x;
        h1.y = a1.y + b1.y + ef1.x*we0.y + ef1.y*we1.y + cb.y;
        h1.z = a1.z + b1.z + ef1.x*we0.z + ef1.y*we1.z + cb.z;
        h1.w = a1.w + b1.w + ef1.x*we0.w + ef1.y*we1.w + cb.w;

        float d0 = gelu_exact(h0.x)*w2.x + gelu_exact(h0.y)*w2.y
                 + gelu_exact(h0.z)*w2.z + gelu_exact(h0.w)*w2.w;
        float d1 = gelu_exact(h1.x)*w2.x + gelu_exact(h1.y)*w2.y
                 + gelu_exact(h1.z)*w2.z + gelu_exact(h1.w)*w2.w;

        #pragma unroll
        for (int off = 16; off > 0; off >>= 1) {
            d0 += __shfl_xor_sync(0xffffffffu, d0, off);
            d1 += __shfl_xor_sync(0xffffffffu, d1, off);
        }

        float c0 = w_0 / (1.f + __expf(-(d0 + b2)));
        float c1 = w_1 / (1.f + __expf(-(d1 + b2)));

        red_add_v4(g_agg + (size_t)dst0*DIM + lane*4,
                   x0.x*c0, x0.y*c0, x0.z*c0, x0.w*c0);
        if (has1)
            red_add_v4(g_agg + (size_t)dst1*DIM + lane*4,
                       x1.x*c1, x1.y*c1, x1.z*c1, x1.w*c1);
    }
}

// ---------------------------------------------------------------------------
// Update GEMM + fused epilogue (agg phase first, x phase last so Xs holds x):
//   h = gelu(x@Wu[:128] + agg@Wu[128:] + b_u); y = x + h; out = LN(y)
// ---------------------------------------------------------------------------
__global__ void __launch_bounds__(256, 2) update_kernel(
    const float* __restrict__ x, const float* __restrict__ Wu,
    const float* __restrict__ bu,
    const float* __restrict__ lng, const float* __restrict__ lnb,
    float* __restrict__ out, int M)
{
    extern __shared__ float sm[];
    float* Ws = sm;
    float* Xs = sm + DIM*DIM;

    int t = threadIdx.x, lane = t & 31, warp = t >> 5;
    int m0 = blockIdx.x * BM, r0 = warp * 8;
    int c0 = lane * 4;

    u64 acc[8][2];
    #pragma unroll
    for (int i = 0; i < 8; i++) { acc[i][0] = 0ull; acc[i][1] = 0ull; }

    #pragma unroll 1
    for (int p = 0; p < 2; p++) {
        const float* src = (p == 0) ? (const float*)g_agg : x;
        const float* W   = Wu + ((p == 0) ? DIM*DIM : 0);

        if (p) __syncthreads();          // previous compute done before overwrite
        load_W_tile(Ws, W, t);
        load_X_tile(Xs, src, t, m0, M);
        __syncthreads();

        gemm_core(Ws, Xs, lane, r0, acc);
    }

    // epilogue: Xs holds the x tile. y = x + gelu(acc + bu), then LN per row.
    float4 bb = *(const float4*)(bu + c0);
    float av[8][4];
    float sums[8], sqs[8];

    #pragma unroll
    for (int i = 0; i < 8; i++) {
        float2 p0 = unpack2(acc[i][0]);
        float2 p1 = unpack2(acc[i][1]);
        float4 xv = *(const float4*)(Xs + (r0 + i)*XSTR + c0);
        float y0 = xv.x + gelu_exact(p0.x + bb.x);
        float y1 = xv.y + gelu_exact(p0.y + bb.y);
        float y2 = xv.z + gelu_exact(p1.x + bb.z);
        float y3 = xv.w + gelu_exact(p1.y + bb.w);
        av[i][0] = y0; av[i][1] = y1; av[i][2] = y2; av[i][3] = y3;
        sums[i] = y0 + y1 + y2 + y3;
        sqs[i]  = y0*y0 + y1*y1 + y2*y2 + y3*y3;
    }
    #pragma unroll
    for (int off = 16; off > 0; off >>= 1) {
        #pragma unroll
        for (int i = 0; i < 8; i++) {
            sums[i] += __shfl_xor_sync(0xffffffffu, sums[i], off);
            sqs[i]  += __shfl_xor_sync(0xffffffffu, sqs[i],  off);
        }
    }
    float4 lg = *(const float4*)(lng + c0);
    float4 lb = *(const float4*)(lnb + c0);

    #pragma unroll
    for (int i = 0; i < 8; i++) {
        float mu  = sums[i] * (1.f / DIM);
        float var = sqs[i] * (1.f / DIM) - mu * mu;
        float rs  = rsqrtf(var + EPS);
        int row = m0 + r0 + i;
        if (row < M) {
            float4 v;
            v.x = (av[i][0] - mu) * rs * lg.x + lb.x;
            v.y = (av[i][1] - mu) * rs * lg.y + lb.y;
            v.z = (av[i][2] - mu) * rs * lg.z + lb.z;
            v.w = (av[i][3] - mu) * rs * lg.w + lb.w;
            ((float4*)out)[(size_t)row*32 + lane] = v;
        }
    }
}

// ---------------------------------------------------------------------------
extern "C" void kernel_launch(void* const* d_in, const int* in_sizes, int n_in,
                              void* d_out, int out_size)
{
    const float* x    = (const float*)d_in[0];
    const int*   ei   = (const int*)  d_in[1];
    const float* ew   = (const float*)d_in[2];
    const float* ef   = (const float*)d_in[3];
    const float* Wphi = (const float*)d_in[5];
    const float* bphi = (const float*)d_in[6];
    const float* Wg1  = (const float*)d_in[7];
    const float* bg1  = (const float*)d_in[8];
    const float* bng  = (const float*)d_in[9];
    const float* bnb  = (const float*)d_in[10];
    const float* bnm  = (const float*)d_in[11];
    const float* bnv  = (const float*)d_in[12];
    const float* Wg2  = (const float*)d_in[13];
    const float* bg2  = (const float*)d_in[14];
    const float* Wu   = (const float*)d_in[15];
    const float* bu   = (const float*)d_in[16];
    const float* lng  = (const float*)d_in[17];
    const float* lnb  = (const float*)d_in[18];
    float* out = (float*)d_out;

    int M = in_sizes[0] / DIM;
    int E = in_sizes[2];
    if (M > MAXN) return;

    cudaFuncSetAttribute(node_fused,    cudaFuncAttributeMaxDynamicSharedMemorySize, SMEM_BYTES);
    cudaFuncSetAttribute(update_kernel, cudaFuncAttributeMaxDynamicSharedMemorySize, SMEM_BYTES);

    void* aggp = nullptr;
    cudaGetSymbolAddress(&aggp, g_agg);
    cudaMemsetAsync(aggp, 0, (size_t)M * DIM * sizeof(float), 0);

    param_kernel<<<1, DIM>>>(Wg1, bg1, bng, bnb, bnm, bnv);

    node_fused<<<(M + BM - 1) / BM, 256, SMEM_BYTES>>>(x, Wphi, bphi, Wg1, bng, bnv, M);

    edge_kernel<<<2368, 256>>>(ei, ew, ef, Wg2, bg2, E);

    update_kernel<<<(M + BM - 1) / BM, 256, SMEM_BYTES>>>(x, Wu, bu, lng, lnb, out, M);
}